// round 15
// baseline (speedup 1.0000x reference)
#include <cuda_runtime.h>
#include <cuda_fp16.h>
#include <math.h>

#define Bsz  2
#define Nseq 2048
#define Emb  1024
#define Hh   16
#define Dd   64
#define Mrows 4096
#define E3   3072
#define Emb2 512          // Emb/2  (packed pairs)
#define D2   32           // Dd/2

// Packed half2-in-uint scratch (scalar 32-bit global access only — safe envelope).
__device__ unsigned g_xh[Mrows * Emb2];          // x packed along E
__device__ unsigned g_wqh[Emb2 * E3];            // w_qkv packed along k (rows)
__device__ unsigned g_wph[Emb2 * Emb];           // w_proj packed along k
__device__ unsigned g_qh[Bsz * Hh * Nseq * D2];  // [B,H,N,D/2]
__device__ unsigned g_kh[Bsz * Hh * Nseq * D2];
__device__ unsigned g_vh[Bsz * Hh * Nseq * D2];
__device__ unsigned g_aoh[Mrows * Emb2];         // attention out packed [B*N, E/2]

__device__ __forceinline__ unsigned pack2(float lo, float hi) {
    unsigned ul = (unsigned)__half_as_ushort(__float2half_rn(lo));
    unsigned uh = (unsigned)__half_as_ushort(__float2half_rn(hi));
    return ul | (uh << 16);
}

// ---------------------------------------------------------------------------
// Prep kernels: pack fp32 inputs to half2 uints ONCE per launch.
// ---------------------------------------------------------------------------
__global__ __launch_bounds__(256) void pack_x_kernel(const float* __restrict__ x)
{
    const int i = blockIdx.x * 256 + threadIdx.x;
    g_xh[i] = pack2(x[2 * i], x[2 * i + 1]);
}

__global__ __launch_bounds__(256) void pack_wq_kernel(const float* __restrict__ w)
{
    const int i = blockIdx.x * 256 + threadIdx.x;
    const int k2 = i / E3;
    const int n  = i - k2 * E3;
    g_wqh[i] = pack2(w[k2 * (2 * E3) + n], w[k2 * (2 * E3) + E3 + n]);
}

__global__ __launch_bounds__(256) void pack_wp_kernel(const float* __restrict__ w)
{
    const int i = blockIdx.x * 256 + threadIdx.x;
    const int k2 = i >> 10;
    const int n  = i & (Emb - 1);
    g_wph[i] = pack2(w[k2 * (2 * Emb) + n], w[k2 * (2 * Emb) + Emb + n]);
}

// ---------------------------------------------------------------------------
// ldmatrix + fp16 m16n8k16 mma macros
// ---------------------------------------------------------------------------
#define LDSM4(dst, addr_)                                                     \
    asm volatile(                                                             \
        "ldmatrix.sync.aligned.m8n8.x4.shared.b16 {%0,%1,%2,%3}, [%4];"       \
        : "=r"((dst).x), "=r"((dst).y), "=r"((dst).z), "=r"((dst).w)          \
        : "r"(addr_));

#define MMA1(mt, nt)                                                          \
    asm volatile(                                                             \
        "mma.sync.aligned.m16n8k16.row.col.f32.f16.f16.f32 "                  \
        "{%0,%1,%2,%3}, {%4,%5,%6,%7}, {%8,%9}, {%0,%1,%2,%3};\n"             \
        : "+f"(c##mt##nt.x), "+f"(c##mt##nt.y),                               \
          "+f"(c##mt##nt.z), "+f"(c##mt##nt.w)                                \
        : "r"(a##mt.x), "r"(a##mt.y), "r"(a##mt.z), "r"(a##mt.w),             \
          "r"(b##nt.x), "r"(b##nt.y))

#define LDA(mt)                                                               \
    uint4 a##mt;                                                              \
    LDSM4(a##mt, aSm + 4u * (unsigned)(bufc * 2560 +                          \
          (wm + mt * 16 + lrow) * 20 + kk2 + lcol4));

#define LDB(nt)                                                               \
    uint2 b##nt;                                                              \
    {                                                                         \
        const int col_ = wn + nt * 8 + g;                                     \
        b##nt.x = Bsu[bufc][kk2 + tig][col_];                                 \
        b##nt.y = Bsu[bufc][kk2 + tig + 4][col_];                             \
    }

#define DEF_C(mt)                                                             \
    float4 c##mt##0 = {0.f,0.f,0.f,0.f}, c##mt##1 = {0.f,0.f,0.f,0.f},        \
           c##mt##2 = {0.f,0.f,0.f,0.f}, c##mt##3 = {0.f,0.f,0.f,0.f};

__device__ __forceinline__ void qkv_store2(int row, int col, float v0, float v1) {
    const int part = col >> 10;           // 0=q,1=k,2=v
    const int h    = (col >> 6) & (Hh - 1);
    const int d2   = (col & (Dd - 1)) >> 1;
    const int bb   = row >> 11;
    const int tok  = row & (Nseq - 1);
    unsigned* dst = (part == 0) ? g_qh : ((part == 1) ? g_kh : g_vh);
    dst[(((bb * Hh + h) * Nseq) + tok) * D2 + d2] = pack2(v0, v1);
}

#define EPIQ(mt, nt)                                                          \
    {                                                                         \
        const int row_ = m0 + wm + mt * 16 + g;                               \
        const int col_ = n0 + wn + nt * 8 + 2 * tig;                          \
        qkv_store2(row_,     col_, c##mt##nt.x + bias[col_], c##mt##nt.y + bias[col_ + 1]); \
        qkv_store2(row_ + 8, col_, c##mt##nt.z + bias[col_], c##mt##nt.w + bias[col_ + 1]); \
    }

#define EPIP(mt, nt)                                                          \
    {                                                                         \
        const int row_ = m0 + wm + mt * 16 + g;                               \
        const int col_ = n0 + wn + nt * 8 + 2 * tig;                          \
        out[row_ * Emb + col_]           = c##mt##nt.x + bias[col_];          \
        out[row_ * Emb + col_ + 1]       = c##mt##nt.y + bias[col_ + 1];      \
        out[(row_ + 8) * Emb + col_]     = c##mt##nt.z + bias[col_];          \
        out[(row_ + 8) * Emb + col_ + 1] = c##mt##nt.w + bias[col_ + 1];      \
    }

#define GEMM_IDX                                                              \
    const int tid  = threadIdx.x;                                             \
    const int lane = tid & 31;                                                \
    const int w    = tid >> 5;                                                \
    const int g    = lane >> 2;                                               \
    const int tig  = lane & 3;                                                \
    const int wm   = (w >> 2) * 64;                                           \
    const int wn   = (w & 3) * 32;                                            \
    const int m0   = blockIdx.y * 128;                                        \
    const int n0   = blockIdx.x * 128;                                        \
    const int lrow = lane & 15;                                               \
    const int lcol4 = (lane >> 4) << 2;                                       \
    const int am   = tid >> 4;                                                \
    const int ak2  = tid & 15;                                                \
    const int bn   = tid & 127;                                               \
    const int bq   = tid >> 7;

#define LGA(j, koff2) pa##j = AELU(am + 16*(j), (koff2) + ak2);
#define LGB(j, koff2) pb##j = BELU((koff2) + bq + 2*(j), bn);
#define LG8(koff2) LGA(0,koff2) LGA(1,koff2) LGA(2,koff2) LGA(3,koff2)        \
                   LGA(4,koff2) LGA(5,koff2) LGA(6,koff2) LGA(7,koff2)        \
                   LGB(0,koff2) LGB(1,koff2) LGB(2,koff2) LGB(3,koff2)        \
                   LGB(4,koff2) LGB(5,koff2) LGB(6,koff2) LGB(7,koff2)
#define STA(j, bf) As2u[bf][am + 16*(j)][ak2] = pa##j;
#define STB(j, bf) Bsu[bf][bq + 2*(j)][bn] = pb##j;
#define ST8(bf) STA(0,bf) STA(1,bf) STA(2,bf) STA(3,bf)                       \
                STA(4,bf) STA(5,bf) STA(6,bf) STA(7,bf)                       \
                STB(0,bf) STB(1,bf) STB(2,bf) STB(3,bf)                       \
                STB(4,bf) STB(5,bf) STB(6,bf) STB(7,bf)

#define GEMM_MAIN_BODY                                                        \
    __shared__ unsigned As2u[2][128][20];                                     \
    __shared__ unsigned Bsu[2][16][136];                                      \
    GEMM_IDX                                                                  \
    const unsigned aSm = (unsigned)__cvta_generic_to_shared(&As2u[0][0][0]);  \
    DEF_C(0) DEF_C(1) DEF_C(2) DEF_C(3)                                       \
    unsigned pa0,pa1,pa2,pa3,pa4,pa5,pa6,pa7;                                 \
    unsigned pb0,pb1,pb2,pb3,pb4,pb5,pb6,pb7;                                 \
    LG8(0)                                                                    \
    ST8(0)                                                                    \
    __syncthreads();                                                          \
    for (int k2c = 0; k2c < Emb2; k2c += 16) {                                \
        const int bufc = (k2c >> 4) & 1;                                      \
        const bool more = (k2c + 16 < Emb2);                                  \
        if (more) { LG8(k2c + 16) }                                           \
        _Pragma("unroll")                                                     \
        for (int ks = 0; ks < 2; ks++) {                                      \
            const int kk2 = ks * 8;                                           \
            LDA(0) LDA(1) LDA(2) LDA(3)                                       \
            LDB(0) LDB(1) LDB(2) LDB(3)                                       \
            MMA1(0,0); MMA1(0,1); MMA1(0,2); MMA1(0,3);                       \
            MMA1(1,0); MMA1(1,1); MMA1(1,2); MMA1(1,3);                       \
            MMA1(2,0); MMA1(2,1); MMA1(2,2); MMA1(2,3);                       \
            MMA1(3,0); MMA1(3,1); MMA1(3,2); MMA1(3,3);                       \
        }                                                                     \
        if (more) { const int nb = bufc ^ 1; ST8(nb) }                        \
        __syncthreads();                                                      \
    }

// ---------------------------------------------------------------------------
// QKV GEMM: xh[4096,512] @ wqh[512,3072] + bias -> packed q/k/v
// ---------------------------------------------------------------------------
__global__ __launch_bounds__(256) void qkv_hmma(const float* __restrict__ bias)
{
#define AELU(mr, kc2) g_xh[(m0 + (mr)) * Emb2 + (kc2)]
#define BELU(kr2, nc) g_wqh[(kr2) * E3 + n0 + (nc)]
    GEMM_MAIN_BODY
#undef AELU
#undef BELU
    EPIQ(0,0) EPIQ(0,1) EPIQ(0,2) EPIQ(0,3)
    EPIQ(1,0) EPIQ(1,1) EPIQ(1,2) EPIQ(1,3)
    EPIQ(2,0) EPIQ(2,1) EPIQ(2,2) EPIQ(2,3)
    EPIQ(3,0) EPIQ(3,1) EPIQ(3,2) EPIQ(3,3)
}

// ---------------------------------------------------------------------------
// Output projection: aoh[4096,512] @ wph[512,1024] + bias -> d_out (fp32)
// ---------------------------------------------------------------------------
__global__ __launch_bounds__(256) void proj_hmma(
    const float* __restrict__ bias, float* __restrict__ out)
{
#define AELU(mr, kc2) g_aoh[(m0 + (mr)) * Emb2 + (kc2)]
#define BELU(kr2, nc) g_wph[(kr2) * Emb + n0 + (nc)]
    GEMM_MAIN_BODY
#undef AELU
#undef BELU
    EPIP(0,0) EPIP(0,1) EPIP(0,2) EPIP(0,3)
    EPIP(1,0) EPIP(1,1) EPIP(1,2) EPIP(1,3)
    EPIP(2,0) EPIP(2,1) EPIP(2,2) EPIP(2,3)
    EPIP(3,0) EPIP(3,1) EPIP(3,2) EPIP(3,3)
}

// ---------------------------------------------------------------------------
// Flash attention, fp16 mma. Block = 128 queries x (b,h); 8 warps x 16 queries.
// Q frags hoisted to registers (loaded once); K/V register-staged prefetch
// overlaps next tile's global loads with this tile's compute.
// ---------------------------------------------------------------------------
#define SCL 0.18033688f    // 0.125 * log2(e)

#define MMA_FRQ(sacc, qv, bx, by)                                             \
    asm volatile(                                                             \
        "mma.sync.aligned.m16n8k16.row.col.f32.f16.f16.f32 "                  \
        "{%0,%1,%2,%3}, {%4,%5,%6,%7}, {%8,%9}, {%0,%1,%2,%3};\n"             \
        : "+f"(sacc.x), "+f"(sacc.y), "+f"(sacc.z), "+f"(sacc.w)              \
        : "r"((qv).x), "r"((qv).y), "r"((qv).z), "r"((qv).w),                 \
          "r"(bx), "r"(by));

// two key-groups worth of B-frags from one ldmatrix.x4
#define SBLK(kk2, qv, sA, sB, roff)                                           \
    {                                                                         \
        uint4 kb;                                                             \
        LDSM4(kb, kSm + 4u * (unsigned)(((roff) + krow) * 36 + (kk2) + kcol4)); \
        MMA_FRQ(sA, qv, kb.x, kb.y) MMA_FRQ(sB, qv, kb.z, kb.w)               \
    }

#define MMA_OV(nt)                                                            \
    {                                                                         \
        const int d2_ = nt * 4 + (g >> 1);                                    \
        const unsigned bx = __byte_perm(Vsu[kp0][d2_],   Vsu[kp0+1][d2_], psel); \
        const unsigned by = __byte_perm(Vsu[kp0+8][d2_], Vsu[kp0+9][d2_], psel); \
        asm volatile(                                                         \
            "mma.sync.aligned.m16n8k16.row.col.f32.f16.f16.f32 "              \
            "{%0,%1,%2,%3}, {%4,%5,%6,%7}, {%8,%9}, {%0,%1,%2,%3};\n"         \
            : "+f"(o##nt.x), "+f"(o##nt.y), "+f"(o##nt.z), "+f"(o##nt.w)      \
            : "r"(a0), "r"(a1), "r"(a2), "r"(a3), "r"(bx), "r"(by));          \
    }

#define PVSTEP(kt, sa, sb)                                                    \
    {                                                                         \
        const unsigned a0 = pack2(sa.x, sa.y);                                \
        const unsigned a1 = pack2(sa.z, sa.w);                                \
        const unsigned a2 = pack2(sb.x, sb.y);                                \
        const unsigned a3 = pack2(sb.z, sb.w);                                \
        const int kp0 = (kt) * 16 + 2 * tig;                                  \
        MMA_OV(0) MMA_OV(1) MMA_OV(2) MMA_OV(3)                               \
        MMA_OV(4) MMA_OV(5) MMA_OV(6) MMA_OV(7)                               \
    }

#define SMAX(nt)                                                              \
    { s##nt.x *= SCL; s##nt.y *= SCL; s##nt.z *= SCL; s##nt.w *= SCL;         \
      mx0 = fmaxf(mx0, fmaxf(s##nt.x, s##nt.y));                              \
      mx1 = fmaxf(mx1, fmaxf(s##nt.z, s##nt.w)); }

#define SEXP(nt)                                                              \
    { s##nt.x = exp2f(s##nt.x - nm0); s##nt.y = exp2f(s##nt.y - nm0);         \
      s##nt.z = exp2f(s##nt.z - nm1); s##nt.w = exp2f(s##nt.w - nm1);         \
      sum0 += s##nt.x + s##nt.y; sum1 += s##nt.z + s##nt.w; }

#define OCORR(nt)                                                             \
    { o##nt.x *= corr0; o##nt.y *= corr0; o##nt.z *= corr1; o##nt.w *= corr1; }

#define OSTORE(nt)                                                            \
    { dst0[nt * 4 + tig] = pack2(o##nt.x * inv0, o##nt.y * inv0);             \
      dst1[nt * 4 + tig] = pack2(o##nt.z * inv1, o##nt.w * inv1); }

// K/V register-staged prefetch
#define KVLD(j) { const int e = tid + (j) * 256; kst##j = Kt[e]; vst##j = Vt[e]; }
#define KVLD8   KVLD(0) KVLD(1) KVLD(2) KVLD(3) KVLD(4) KVLD(5) KVLD(6) KVLD(7)
#define KVST(j) { const int e = tid + (j) * 256;                              \
                  Ksu[e >> 5][e & 31] = kst##j; Vsu[e >> 5][e & 31] = vst##j; }
#define KVST8   KVST(0) KVST(1) KVST(2) KVST(3) KVST(4) KVST(5) KVST(6) KVST(7)

__global__ __launch_bounds__(256) void attn_hmma()
{
    __shared__ unsigned Qsu[128][36];  // [q][d2]
    __shared__ unsigned Ksu[64][36];   // [key][d2]
    __shared__ unsigned Vsu[64][36];   // [key][d2]

    const int tid  = threadIdx.x;
    const int lane = tid & 31;
    const int w    = tid >> 5;          // warp 0..7 -> queries [16w,16w+16)
    const int g    = lane >> 2;
    const int tig  = lane & 3;
    const int bh   = blockIdx.y;
    const int q0   = blockIdx.x * 128;
    const int qr   = w * 16 + g;
    const unsigned psel = (g & 1) ? 0x7632u : 0x5410u;
    const int lrow  = lane & 15;
    const int lcol4 = (lane >> 4) << 2;
    const int krow  = ((lane >> 4) << 3) + (lane & 7);
    const int kcol4 = ((lane >> 3) & 1) << 2;

    const unsigned* Qg = g_qh + (size_t)(bh * Nseq + q0) * D2;
    const unsigned* Kg = g_kh + (size_t)bh * Nseq * D2;
    const unsigned* Vg = g_vh + (size_t)bh * Nseq * D2;

    #pragma unroll
    for (int u = 0; u < 16; u++) {
        const int e = tid + u * 256;
        Qsu[e >> 5][e & 31] = Qg[e];
    }

    // stage tile 0
    unsigned kst0,kst1,kst2,kst3,kst4,kst5,kst6,kst7;
    unsigned vst0,vst1,vst2,vst3,vst4,vst5,vst6,vst7;
    {
        const unsigned* Kt = Kg;
        const unsigned* Vt = Vg;
        KVLD8
    }

    const unsigned qSm = (unsigned)__cvta_generic_to_shared(&Qsu[0][0]);
    const unsigned kSm = (unsigned)__cvta_generic_to_shared(&Ksu[0][0]);

    float m0r = -INFINITY, m1r = -INFINITY, l0 = 0.0f, l1 = 0.0f;
    float4 o0 = {0.f,0.f,0.f,0.f}, o1 = {0.f,0.f,0.f,0.f},
           o2 = {0.f,0.f,0.f,0.f}, o3 = {0.f,0.f,0.f,0.f},
           o4 = {0.f,0.f,0.f,0.f}, o5 = {0.f,0.f,0.f,0.f},
           o6 = {0.f,0.f,0.f,0.f}, o7 = {0.f,0.f,0.f,0.f};
    __syncthreads();   // Qsu visible

    // hoist Q fragments (tile-invariant)
    uint4 qa0, qa1, qa2, qa3;
    LDSM4(qa0, qSm + 4u * (unsigned)((w * 16 + lrow) * 36 + 0  + lcol4));
    LDSM4(qa1, qSm + 4u * (unsigned)((w * 16 + lrow) * 36 + 8  + lcol4));
    LDSM4(qa2, qSm + 4u * (unsigned)((w * 16 + lrow) * 36 + 16 + lcol4));
    LDSM4(qa3, qSm + 4u * (unsigned)((w * 16 + lrow) * 36 + 24 + lcol4));

    for (int t = 0; t < Nseq / 64; t++) {
        KVST8
        __syncthreads();   // K/V tile visible

        // prefetch next tile into registers (overlaps all compute below)
        if (t + 1 < Nseq / 64) {
            const unsigned* Kt = Kg + (t + 1) * 64 * D2;
            const unsigned* Vt = Vg + (t + 1) * 64 * D2;
            KVLD8
        }

        // S = Q @ K^T  (16q x 64key per warp)
        float4 s0 = {0.f,0.f,0.f,0.f}, s1 = {0.f,0.f,0.f,0.f},
               s2 = {0.f,0.f,0.f,0.f}, s3 = {0.f,0.f,0.f,0.f},
               s4 = {0.f,0.f,0.f,0.f}, s5 = {0.f,0.f,0.f,0.f},
               s6 = {0.f,0.f,0.f,0.f}, s7 = {0.f,0.f,0.f,0.f};
        SBLK(0,  qa0, s0, s1, 0)  SBLK(0,  qa0, s2, s3, 16)
        SBLK(0,  qa0, s4, s5, 32) SBLK(0,  qa0, s6, s7, 48)
        SBLK(8,  qa1, s0, s1, 0)  SBLK(8,  qa1, s2, s3, 16)
        SBLK(8,  qa1, s4, s5, 32) SBLK(8,  qa1, s6, s7, 48)
        SBLK(16, qa2, s0, s1, 0)  SBLK(16, qa2, s2, s3, 16)
        SBLK(16, qa2, s4, s5, 32) SBLK(16, qa2, s6, s7, 48)
        SBLK(24, qa3, s0, s1, 0)  SBLK(24, qa3, s2, s3, 16)
        SBLK(24, qa3, s4, s5, 32) SBLK(24, qa3, s6, s7, 48)

        // online softmax in log2 domain (rows qr, qr+8)
        float mx0 = -INFINITY, mx1 = -INFINITY;
        SMAX(0) SMAX(1) SMAX(2) SMAX(3) SMAX(4) SMAX(5) SMAX(6) SMAX(7)
        mx0 = fmaxf(mx0, __shfl_xor_sync(0xffffffffu, mx0, 1));
        mx0 = fmaxf(mx0, __shfl_xor_sync(0xffffffffu, mx0, 2));
        mx1 = fmaxf(mx1, __shfl_xor_sync(0xffffffffu, mx1, 1));
        mx1 = fmaxf(mx1, __shfl_xor_sync(0xffffffffu, mx1, 2));
        const float nm0 = fmaxf(m0r, mx0);
        const float nm1 = fmaxf(m1r, mx1);
        float sum0 = 0.0f, sum1 = 0.0f;
        SEXP(0) SEXP(1) SEXP(2) SEXP(3) SEXP(4) SEXP(5) SEXP(6) SEXP(7)
        sum0 += __shfl_xor_sync(0xffffffffu, sum0, 1);
        sum0 += __shfl_xor_sync(0xffffffffu, sum0, 2);
        sum1 += __shfl_xor_sync(0xffffffffu, sum1, 1);
        sum1 += __shfl_xor_sync(0xffffffffu, sum1, 2);
        const float corr0 = exp2f(m0r - nm0);   // exp2(-inf)=0 first iter
        const float corr1 = exp2f(m1r - nm1);
        l0 = l0 * corr0 + sum0;
        l1 = l1 * corr1 + sum1;
        m0r = nm0; m1r = nm1;
        OCORR(0) OCORR(1) OCORR(2) OCORR(3) OCORR(4) OCORR(5) OCORR(6) OCORR(7)

        // O += P @ V  — P passed register-to-register
        PVSTEP(0, s0, s1)
        PVSTEP(1, s2, s3)
        PVSTEP(2, s4, s5)
        PVSTEP(3, s6, s7)
        __syncthreads();   // done reading Ksu/Vsu before next KVST8
    }

    // epilogue: normalize + packed store to g_aoh [B*N, E/2]
    const int bb = bh >> 4;
    const int h  = bh & (Hh - 1);
    const float inv0 = 1.0f / l0;
    const float inv1 = 1.0f / l1;
    const int row0 = q0 + qr;
    unsigned* dst0 = &g_aoh[(size_t)(bb * Nseq + row0) * Emb2 + h * D2];
    unsigned* dst1 = &g_aoh[(size_t)(bb * Nseq + row0 + 8) * Emb2 + h * D2];
    OSTORE(0) OSTORE(1) OSTORE(2) OSTORE(3)
    OSTORE(4) OSTORE(5) OSTORE(6) OSTORE(7)
}

// ---------------------------------------------------------------------------
extern "C" void kernel_launch(void* const* d_in, const int* in_sizes, int n_in,
                              void* d_out, int out_size)
{
    const float* x      = (const float*)d_in[0];
    const float* w_qkv  = (const float*)d_in[1];
    const float* b_qkv  = (const float*)d_in[2];
    const float* w_proj = (const float*)d_in[3];
    const float* b_proj = (const float*)d_in[4];
    float* out = (float*)d_out;

    pack_x_kernel <<<(Mrows * Emb2) / 256, 256>>>(x);
    pack_wq_kernel<<<(Emb2 * E3)   / 256, 256>>>(w_qkv);
    pack_wp_kernel<<<(Emb2 * Emb)  / 256, 256>>>(w_proj);

    qkv_hmma<<<dim3(E3 / 128, Mrows / 128), 256>>>(b_qkv);
    attn_hmma<<<dim3(Nseq / 128, Bsz * Hh), 256>>>();
    proj_hmma<<<dim3(Emb / 128, Mrows / 128), 256>>>(b_proj, out);
}

// round 16
// speedup vs baseline: 1.1086x; 1.1086x over previous
#include <cuda_runtime.h>
#include <cuda_fp16.h>
#include <math.h>

#define Bsz  2
#define Nseq 2048
#define Emb  1024
#define Hh   16
#define Dd   64
#define Mrows 4096
#define E3   3072
#define Emb2 512          // Emb/2  (packed pairs)
#define D2   32           // Dd/2
#define N2   1024         // Nseq/2 (packed key pairs)

// Packed half2-in-uint scratch (scalar 32-bit global access; V^T uses scalar
// 16-bit stores + scalar 32-bit loads — all within the safe envelope).
__device__ unsigned g_xh[Mrows * Emb2];          // x packed along E
__device__ unsigned g_wqh[Emb2 * E3];            // w_qkv packed along k (rows)
__device__ unsigned g_wph[Emb2 * Emb];           // w_proj packed along k
__device__ unsigned g_qh[Bsz * Hh * Nseq * D2];  // [B,H,N,D/2]
__device__ unsigned g_kh[Bsz * Hh * Nseq * D2];
__device__ unsigned short g_vt[Bsz * Hh * Dd * Nseq];  // V^T [B,H,D,N] fp16
__device__ unsigned g_aoh[Mrows * Emb2];         // attention out packed [B*N, E/2]

// single-instruction pack: two f32 -> f16x2 (d.lo = lo, d.hi = hi)
__device__ __forceinline__ unsigned pack2(float lo, float hi) {
    unsigned u;
    asm("cvt.rn.f16x2.f32 %0, %1, %2;" : "=r"(u) : "f"(hi), "f"(lo));
    return u;
}

// ---------------------------------------------------------------------------
// Prep kernels: pack fp32 inputs to half2 uints ONCE per launch.
// ---------------------------------------------------------------------------
__global__ __launch_bounds__(256) void pack_x_kernel(const float* __restrict__ x)
{
    const int i = blockIdx.x * 256 + threadIdx.x;
    g_xh[i] = pack2(x[2 * i], x[2 * i + 1]);
}

__global__ __launch_bounds__(256) void pack_wq_kernel(const float* __restrict__ w)
{
    const int i = blockIdx.x * 256 + threadIdx.x;
    const int k2 = i / E3;
    const int n  = i - k2 * E3;
    g_wqh[i] = pack2(w[k2 * (2 * E3) + n], w[k2 * (2 * E3) + E3 + n]);
}

__global__ __launch_bounds__(256) void pack_wp_kernel(const float* __restrict__ w)
{
    const int i = blockIdx.x * 256 + threadIdx.x;
    const int k2 = i >> 10;
    const int n  = i & (Emb - 1);
    g_wph[i] = pack2(w[k2 * (2 * Emb) + n], w[k2 * (2 * Emb) + Emb + n]);
}

// ---------------------------------------------------------------------------
// ldmatrix + fp16 m16n8k16 mma macros
// ---------------------------------------------------------------------------
#define LDSM4(dst, addr_)                                                     \
    asm volatile(                                                             \
        "ldmatrix.sync.aligned.m8n8.x4.shared.b16 {%0,%1,%2,%3}, [%4];"       \
        : "=r"((dst).x), "=r"((dst).y), "=r"((dst).z), "=r"((dst).w)          \
        : "r"(addr_));

#define MMA1(mt, nt)                                                          \
    asm volatile(                                                             \
        "mma.sync.aligned.m16n8k16.row.col.f32.f16.f16.f32 "                  \
        "{%0,%1,%2,%3}, {%4,%5,%6,%7}, {%8,%9}, {%0,%1,%2,%3};\n"             \
        : "+f"(c##mt##nt.x), "+f"(c##mt##nt.y),                               \
          "+f"(c##mt##nt.z), "+f"(c##mt##nt.w)                                \
        : "r"(a##mt.x), "r"(a##mt.y), "r"(a##mt.z), "r"(a##mt.w),             \
          "r"(b##nt.x), "r"(b##nt.y))

#define LDA(mt)                                                               \
    uint4 a##mt;                                                              \
    LDSM4(a##mt, aSm + 4u * (unsigned)(bufc * 2560 +                          \
          (wm + mt * 16 + lrow) * 20 + kk2 + lcol4));

#define LDB(nt)                                                               \
    uint2 b##nt;                                                              \
    {                                                                         \
        const int col_ = wn + nt * 8 + g;                                     \
        b##nt.x = Bsu[bufc][kk2 + tig][col_];                                 \
        b##nt.y = Bsu[bufc][kk2 + tig + 4][col_];                             \
    }

#define DEF_C(mt)                                                             \
    float4 c##mt##0 = {0.f,0.f,0.f,0.f}, c##mt##1 = {0.f,0.f,0.f,0.f},        \
           c##mt##2 = {0.f,0.f,0.f,0.f}, c##mt##3 = {0.f,0.f,0.f,0.f};

// qkv epilogue: q/k packed-pair stores; V transposed fp16 scalar stores
__device__ __forceinline__ void qkv_store2(int row, int col, float v0, float v1) {
    const int part = col >> 10;           // 0=q,1=k,2=v
    const int h    = (col >> 6) & (Hh - 1);
    const int d    = col & (Dd - 1);
    const int bb   = row >> 11;
    const int tok  = row & (Nseq - 1);
    if (part == 2) {
        const size_t base = ((size_t)(bb * Hh + h) * Dd + d) * Nseq + tok;
        g_vt[base]        = __half_as_ushort(__float2half_rn(v0));
        g_vt[base + Nseq] = __half_as_ushort(__float2half_rn(v1));  // d+1 row
    } else {
        unsigned* dst = (part == 0) ? g_qh : g_kh;
        dst[(((bb * Hh + h) * Nseq) + tok) * D2 + (d >> 1)] = pack2(v0, v1);
    }
}

#define EPIQ(mt, nt)                                                          \
    {                                                                         \
        const int row_ = m0 + wm + mt * 16 + g;                               \
        const int col_ = n0 + wn + nt * 8 + 2 * tig;                          \
        qkv_store2(row_,     col_, c##mt##nt.x + bias[col_], c##mt##nt.y + bias[col_ + 1]); \
        qkv_store2(row_ + 8, col_, c##mt##nt.z + bias[col_], c##mt##nt.w + bias[col_ + 1]); \
    }

#define EPIP(mt, nt)                                                          \
    {                                                                         \
        const int row_ = m0 + wm + mt * 16 + g;                               \
        const int col_ = n0 + wn + nt * 8 + 2 * tig;                          \
        out[row_ * Emb + col_]           = c##mt##nt.x + bias[col_];          \
        out[row_ * Emb + col_ + 1]       = c##mt##nt.y + bias[col_ + 1];      \
        out[(row_ + 8) * Emb + col_]     = c##mt##nt.z + bias[col_];          \
        out[(row_ + 8) * Emb + col_ + 1] = c##mt##nt.w + bias[col_ + 1];      \
    }

#define GEMM_IDX                                                              \
    const int tid  = threadIdx.x;                                             \
    const int lane = tid & 31;                                                \
    const int w    = tid >> 5;                                                \
    const int g    = lane >> 2;                                               \
    const int tig  = lane & 3;                                                \
    const int wm   = (w >> 2) * 64;                                           \
    const int wn   = (w & 3) * 32;                                            \
    const int m0   = blockIdx.y * 128;                                        \
    const int n0   = blockIdx.x * 128;                                        \
    const int lrow = lane & 15;                                               \
    const int lcol4 = (lane >> 4) << 2;                                       \
    const int am   = tid >> 4;                                                \
    const int ak2  = tid & 15;                                                \
    const int bn   = tid & 127;                                               \
    const int bq   = tid >> 7;

#define LGA(j, koff2) pa##j = AELU(am + 16*(j), (koff2) + ak2);
#define LGB(j, koff2) pb##j = BELU((koff2) + bq + 2*(j), bn);
#define LG8(koff2) LGA(0,koff2) LGA(1,koff2) LGA(2,koff2) LGA(3,koff2)        \
                   LGA(4,koff2) LGA(5,koff2) LGA(6,koff2) LGA(7,koff2)        \
                   LGB(0,koff2) LGB(1,koff2) LGB(2,koff2) LGB(3,koff2)        \
                   LGB(4,koff2) LGB(5,koff2) LGB(6,koff2) LGB(7,koff2)
#define STA(j, bf) As2u[bf][am + 16*(j)][ak2] = pa##j;
#define STB(j, bf) Bsu[bf][bq + 2*(j)][bn] = pb##j;
#define ST8(bf) STA(0,bf) STA(1,bf) STA(2,bf) STA(3,bf)                       \
                STA(4,bf) STA(5,bf) STA(6,bf) STA(7,bf)                       \
                STB(0,bf) STB(1,bf) STB(2,bf) STB(3,bf)                       \
                STB(4,bf) STB(5,bf) STB(6,bf) STB(7,bf)

#define GEMM_MAIN_BODY                                                        \
    __shared__ unsigned As2u[2][128][20];                                     \
    __shared__ unsigned Bsu[2][16][136];                                      \
    GEMM_IDX                                                                  \
    const unsigned aSm = (unsigned)__cvta_generic_to_shared(&As2u[0][0][0]);  \
    DEF_C(0) DEF_C(1) DEF_C(2) DEF_C(3)                                       \
    unsigned pa0,pa1,pa2,pa3,pa4,pa5,pa6,pa7;                                 \
    unsigned pb0,pb1,pb2,pb3,pb4,pb5,pb6,pb7;                                 \
    LG8(0)                                                                    \
    ST8(0)                                                                    \
    __syncthreads();                                                          \
    for (int k2c = 0; k2c < Emb2; k2c += 16) {                                \
        const int bufc = (k2c >> 4) & 1;                                      \
        const bool more = (k2c + 16 < Emb2);                                  \
        if (more) { LG8(k2c + 16) }                                           \
        _Pragma("unroll")                                                     \
        for (int ks = 0; ks < 2; ks++) {                                      \
            const int kk2 = ks * 8;                                           \
            LDA(0) LDA(1) LDA(2) LDA(3)                                       \
            LDB(0) LDB(1) LDB(2) LDB(3)                                       \
            MMA1(0,0); MMA1(0,1); MMA1(0,2); MMA1(0,3);                       \
            MMA1(1,0); MMA1(1,1); MMA1(1,2); MMA1(1,3);                       \
            MMA1(2,0); MMA1(2,1); MMA1(2,2); MMA1(2,3);                       \
            MMA1(3,0); MMA1(3,1); MMA1(3,2); MMA1(3,3);                       \
        }                                                                     \
        if (more) { const int nb = bufc ^ 1; ST8(nb) }                        \
        __syncthreads();                                                      \
    }

// ---------------------------------------------------------------------------
// QKV GEMM: xh[4096,512] @ wqh[512,3072] + bias -> packed q/k + V^T
// ---------------------------------------------------------------------------
__global__ __launch_bounds__(256) void qkv_hmma(const float* __restrict__ bias)
{
#define AELU(mr, kc2) g_xh[(m0 + (mr)) * Emb2 + (kc2)]
#define BELU(kr2, nc) g_wqh[(kr2) * E3 + n0 + (nc)]
    GEMM_MAIN_BODY
#undef AELU
#undef BELU
    EPIQ(0,0) EPIQ(0,1) EPIQ(0,2) EPIQ(0,3)
    EPIQ(1,0) EPIQ(1,1) EPIQ(1,2) EPIQ(1,3)
    EPIQ(2,0) EPIQ(2,1) EPIQ(2,2) EPIQ(2,3)
    EPIQ(3,0) EPIQ(3,1) EPIQ(3,2) EPIQ(3,3)
}

// ---------------------------------------------------------------------------
// Output projection: aoh[4096,512] @ wph[512,1024] + bias -> d_out (fp32)
// ---------------------------------------------------------------------------
__global__ __launch_bounds__(256) void proj_hmma(
    const float* __restrict__ bias, float* __restrict__ out)
{
#define AELU(mr, kc2) g_aoh[(m0 + (mr)) * Emb2 + (kc2)]
#define BELU(kr2, nc) g_wph[(kr2) * Emb + n0 + (nc)]
    GEMM_MAIN_BODY
#undef AELU
#undef BELU
    EPIP(0,0) EPIP(0,1) EPIP(0,2) EPIP(0,3)
    EPIP(1,0) EPIP(1,1) EPIP(1,2) EPIP(1,3)
    EPIP(2,0) EPIP(2,1) EPIP(2,2) EPIP(2,3)
    EPIP(3,0) EPIP(3,1) EPIP(3,2) EPIP(3,3)
}

// ---------------------------------------------------------------------------
// Flash attention, fp16 mma. Block = 128 queries x (b,h); 8 warps x 16 queries.
// K smem [key][d2]; V smem TRANSPOSED [d][key2] -> PV B-frags are 2 plain LDS
// (no byte_perm). Q frags hoisted. exp2 softmax. P register-resident.
// ---------------------------------------------------------------------------
#define SCL 0.18033688f    // 0.125 * log2(e)

#define MMA_FRQ(sacc, qv, bx, by)                                             \
    asm volatile(                                                             \
        "mma.sync.aligned.m16n8k16.row.col.f32.f16.f16.f32 "                  \
        "{%0,%1,%2,%3}, {%4,%5,%6,%7}, {%8,%9}, {%0,%1,%2,%3};\n"             \
        : "+f"(sacc.x), "+f"(sacc.y), "+f"(sacc.z), "+f"(sacc.w)              \
        : "r"((qv).x), "r"((qv).y), "r"((qv).z), "r"((qv).w),                 \
          "r"(bx), "r"(by));

// two key-groups worth of K B-frags from one ldmatrix.x4
#define SBLK(kk2, qv, sA, sB, roff)                                           \
    {                                                                         \
        uint4 kb;                                                             \
        LDSM4(kb, kSm + 4u * (unsigned)(((roff) + krow) * 36 + (kk2) + kcol4)); \
        MMA_FRQ(sA, qv, kb.x, kb.y) MMA_FRQ(sB, qv, kb.z, kb.w)               \
    }

// PV mma: B-frag from transposed V smem, plain scalar LDS (conflict-free)
#define MMA_OV(nt)                                                            \
    {                                                                         \
        const unsigned bx = Vsu[nt * 8 + g][kk2v + tig];                      \
        const unsigned by = Vsu[nt * 8 + g][kk2v + tig + 4];                  \
        asm volatile(                                                         \
            "mma.sync.aligned.m16n8k16.row.col.f32.f16.f16.f32 "              \
            "{%0,%1,%2,%3}, {%4,%5,%6,%7}, {%8,%9}, {%0,%1,%2,%3};\n"         \
            : "+f"(o##nt.x), "+f"(o##nt.y), "+f"(o##nt.z), "+f"(o##nt.w)      \
            : "r"(a0), "r"(a1), "r"(a2), "r"(a3), "r"(bx), "r"(by));          \
    }

#define PVSTEP(kt, sa, sb)                                                    \
    {                                                                         \
        const unsigned a0 = pack2(sa.x, sa.y);                                \
        const unsigned a1 = pack2(sa.z, sa.w);                                \
        const unsigned a2 = pack2(sb.x, sb.y);                                \
        const unsigned a3 = pack2(sb.z, sb.w);                                \
        const int kk2v = (kt) * 8;                                            \
        MMA_OV(0) MMA_OV(1) MMA_OV(2) MMA_OV(3)                               \
        MMA_OV(4) MMA_OV(5) MMA_OV(6) MMA_OV(7)                               \
    }

#define SMAX(nt)                                                              \
    { s##nt.x *= SCL; s##nt.y *= SCL; s##nt.z *= SCL; s##nt.w *= SCL;         \
      mx0 = fmaxf(mx0, fmaxf(s##nt.x, s##nt.y));                              \
      mx1 = fmaxf(mx1, fmaxf(s##nt.z, s##nt.w)); }

#define SEXP(nt)                                                              \
    { s##nt.x = exp2f(s##nt.x - nm0); s##nt.y = exp2f(s##nt.y - nm0);         \
      s##nt.z = exp2f(s##nt.z - nm1); s##nt.w = exp2f(s##nt.w - nm1);         \
      sum0 += s##nt.x + s##nt.y; sum1 += s##nt.z + s##nt.w; }

#define OCORR(nt)                                                             \
    { o##nt.x *= corr0; o##nt.y *= corr0; o##nt.z *= corr1; o##nt.w *= corr1; }

#define OSTORE(nt)                                                            \
    { dst0[nt * 4 + tig] = pack2(o##nt.x * inv0, o##nt.y * inv0);             \
      dst1[nt * 4 + tig] = pack2(o##nt.z * inv1, o##nt.w * inv1); }

__global__ __launch_bounds__(256) void attn_hmma()
{
    __shared__ unsigned Qsu[128][36];  // [q][d2]
    __shared__ unsigned Ksu[64][36];   // [key][d2]
    __shared__ unsigned Vsu[64][36];   // [d][key2]  (transposed V)

    const int tid  = threadIdx.x;
    const int lane = tid & 31;
    const int w    = tid >> 5;          // warp 0..7 -> queries [16w,16w+16)
    const int g    = lane >> 2;
    const int tig  = lane & 3;
    const int bh   = blockIdx.y;
    const int q0   = blockIdx.x * 128;
    const int qr   = w * 16 + g;
    const int lrow  = lane & 15;
    const int lcol4 = (lane >> 4) << 2;
    const int krow  = ((lane >> 4) << 3) + (lane & 7);
    const int kcol4 = ((lane >> 3) & 1) << 2;

    const unsigned* Qg = g_qh + (size_t)(bh * Nseq + q0) * D2;
    const unsigned* Kg = g_kh + (size_t)bh * Nseq * D2;
    const unsigned* Vg = reinterpret_cast<const unsigned*>(g_vt)
                         + (size_t)bh * Dd * (Nseq / 2);   // [d][key2]

    #pragma unroll
    for (int u = 0; u < 16; u++) {
        const int e = tid + u * 256;
        Qsu[e >> 5][e & 31] = Qg[e];
    }

    const unsigned qSm = (unsigned)__cvta_generic_to_shared(&Qsu[0][0]);
    const unsigned kSm = (unsigned)__cvta_generic_to_shared(&Ksu[0][0]);

    float m0r = -INFINITY, m1r = -INFINITY, l0 = 0.0f, l1 = 0.0f;
    float4 o0 = {0.f,0.f,0.f,0.f}, o1 = {0.f,0.f,0.f,0.f},
           o2 = {0.f,0.f,0.f,0.f}, o3 = {0.f,0.f,0.f,0.f},
           o4 = {0.f,0.f,0.f,0.f}, o5 = {0.f,0.f,0.f,0.f},
           o6 = {0.f,0.f,0.f,0.f}, o7 = {0.f,0.f,0.f,0.f};
    __syncthreads();   // Qsu visible

    // hoist Q fragments (tile-invariant)
    uint4 qa0, qa1, qa2, qa3;
    LDSM4(qa0, qSm + 4u * (unsigned)((w * 16 + lrow) * 36 + 0  + lcol4));
    LDSM4(qa1, qSm + 4u * (unsigned)((w * 16 + lrow) * 36 + 8  + lcol4));
    LDSM4(qa2, qSm + 4u * (unsigned)((w * 16 + lrow) * 36 + 16 + lcol4));
    LDSM4(qa3, qSm + 4u * (unsigned)((w * 16 + lrow) * 36 + 24 + lcol4));

    for (int t = 0; t < Nseq / 64; t++) {
        const unsigned* Kt = Kg + t * 64 * D2;
        #pragma unroll
        for (int u = 0; u < 8; u++) {
            const int e = tid + u * 256;        // 2048 elements
            Ksu[e >> 5][e & 31] = Kt[e];        // [key][d2]
            const int vr = e >> 5, vc = e & 31; // [d][key2]
            Vsu[vr][vc] = Vg[vr * (Nseq / 2) + t * 32 + vc];
        }
        __syncthreads();

        // S = Q @ K^T  (16q x 64key per warp)
        float4 s0 = {0.f,0.f,0.f,0.f}, s1 = {0.f,0.f,0.f,0.f},
               s2 = {0.f,0.f,0.f,0.f}, s3 = {0.f,0.f,0.f,0.f},
               s4 = {0.f,0.f,0.f,0.f}, s5 = {0.f,0.f,0.f,0.f},
               s6 = {0.f,0.f,0.f,0.f}, s7 = {0.f,0.f,0.f,0.f};
        SBLK(0,  qa0, s0, s1, 0)  SBLK(0,  qa0, s2, s3, 16)
        SBLK(0,  qa0, s4, s5, 32) SBLK(0,  qa0, s6, s7, 48)
        SBLK(8,  qa1, s0, s1, 0)  SBLK(8,  qa1, s2, s3, 16)
        SBLK(8,  qa1, s4, s5, 32) SBLK(8,  qa1, s6, s7, 48)
        SBLK(16, qa2, s0, s1, 0)  SBLK(16, qa2, s2, s3, 16)
        SBLK(16, qa2, s4, s5, 32) SBLK(16, qa2, s6, s7, 48)
        SBLK(24, qa3, s0, s1, 0)  SBLK(24, qa3, s2, s3, 16)
        SBLK(24, qa3, s4, s5, 32) SBLK(24, qa3, s6, s7, 48)

        // online softmax in log2 domain (rows qr, qr+8)
        float mx0 = -INFINITY, mx1 = -INFINITY;
        SMAX(0) SMAX(1) SMAX(2) SMAX(3) SMAX(4) SMAX(5) SMAX(6) SMAX(7)
        mx0 = fmaxf(mx0, __shfl_xor_sync(0xffffffffu, mx0, 1));
        mx0 = fmaxf(mx0, __shfl_xor_sync(0xffffffffu, mx0, 2));
        mx1 = fmaxf(mx1, __shfl_xor_sync(0xffffffffu, mx1, 1));
        mx1 = fmaxf(mx1, __shfl_xor_sync(0xffffffffu, mx1, 2));
        const float nm0 = fmaxf(m0r, mx0);
        const float nm1 = fmaxf(m1r, mx1);
        float sum0 = 0.0f, sum1 = 0.0f;
        SEXP(0) SEXP(1) SEXP(2) SEXP(3) SEXP(4) SEXP(5) SEXP(6) SEXP(7)
        sum0 += __shfl_xor_sync(0xffffffffu, sum0, 1);
        sum0 += __shfl_xor_sync(0xffffffffu, sum0, 2);
        sum1 += __shfl_xor_sync(0xffffffffu, sum1, 1);
        sum1 += __shfl_xor_sync(0xffffffffu, sum1, 2);
        const float corr0 = exp2f(m0r - nm0);   // exp2(-inf)=0 first iter
        const float corr1 = exp2f(m1r - nm1);
        l0 = l0 * corr0 + sum0;
        l1 = l1 * corr1 + sum1;
        m0r = nm0; m1r = nm1;
        OCORR(0) OCORR(1) OCORR(2) OCORR(3) OCORR(4) OCORR(5) OCORR(6) OCORR(7)

        // O += P @ V  — P register-resident, V^T B-frags via plain LDS
        PVSTEP(0, s0, s1)
        PVSTEP(1, s2, s3)
        PVSTEP(2, s4, s5)
        PVSTEP(3, s6, s7)
        __syncthreads();
    }

    // epilogue: normalize + packed store to g_aoh [B*N, E/2]
    const int bb = bh >> 4;
    const int h  = bh & (Hh - 1);
    const float inv0 = 1.0f / l0;
    const float inv1 = 1.0f / l1;
    const int row0 = q0 + qr;
    unsigned* dst0 = &g_aoh[(size_t)(bb * Nseq + row0) * Emb2 + h * D2];
    unsigned* dst1 = &g_aoh[(size_t)(bb * Nseq + row0 + 8) * Emb2 + h * D2];
    OSTORE(0) OSTORE(1) OSTORE(2) OSTORE(3)
    OSTORE(4) OSTORE(5) OSTORE(6) OSTORE(7)
}

// ---------------------------------------------------------------------------
extern "C" void kernel_launch(void* const* d_in, const int* in_sizes, int n_in,
                              void* d_out, int out_size)
{
    const float* x      = (const float*)d_in[0];
    const float* w_qkv  = (const float*)d_in[1];
    const float* b_qkv  = (const float*)d_in[2];
    const float* w_proj = (const float*)d_in[3];
    const float* b_proj = (const float*)d_in[4];
    float* out = (float*)d_out;

    pack_x_kernel <<<(Mrows * Emb2) / 256, 256>>>(x);
    pack_wq_kernel<<<(Emb2 * E3)   / 256, 256>>>(w_qkv);
    pack_wp_kernel<<<(Emb2 * Emb)  / 256, 256>>>(w_proj);

    qkv_hmma<<<dim3(E3 / 128, Mrows / 128), 256>>>(b_qkv);
    attn_hmma<<<dim3(Nseq / 128, Bsz * Hh), 256>>>();
    proj_hmma<<<dim3(Emb / 128, Mrows / 128), 256>>>(b_proj, out);
}